// round 1
// baseline (speedup 1.0000x reference)
#include <cuda_runtime.h>
#include <cuda_bf16.h>

// Problem constants (fixed shapes per reference)
#define NTOKEN 150000
#define NINP   64
#define NEDGE  2400000
#define NPOS_MAX 12800

// ---------------- scratch (static __device__, no allocation) ----------------
__device__ int   g_is64;                       // 1 if index inputs are int64, 0 if int32
__device__ int   g_deg[NTOKEN];                // in-degree (dst counts)
__device__ int   g_off[NTOKEN];                // CSR exclusive offsets
__device__ int   g_cur[NTOKEN];                // scatter cursors
__device__ float g_dinv[NTOKEN];               // 1/sqrt(deg+1)
__device__ int   g_srcs[NEDGE];                // CSR: src ids grouped by dst
__device__ float g_aggX[(size_t)NTOKEN * 64];  // layer-1 aggregated emb (64-dim)
__device__ float g_gv  [(size_t)NTOKEN * 64];  // g = aggX @ Wc + bc (64-dim)
__device__ float g_Wc[64 * 64];                // W1 @ W2
__device__ float g_bc[64];                     // b1 @ W2

// ---------------- helpers ----------------
__device__ __forceinline__ long long load_idx(const void* p, long long i, int is64) {
    if (is64) return ((const long long*)p)[i];
    return (long long)((const int*)p)[i];
}

// Detect int64 vs int32 index encoding: if the buffer is int64, every 8-byte
// word has zero high 32 bits (values in [0, 150000)). If it's int32, the high
// word is a random index — the chance all 64 are zero is ~(6.7e-6)^64.
__global__ void detect_kernel(const void* __restrict__ edge) {
    if (threadIdx.x == 0) {
        const unsigned long long* e = (const unsigned long long*)edge;
        int is64 = 1;
        for (int i = 0; i < 64; i++) {
            if ((e[i] >> 32) != 0ull) { is64 = 0; break; }
        }
        g_is64 = is64;
    }
}

__global__ void zero_deg_kernel() {
    int i = blockIdx.x * blockDim.x + threadIdx.x;
    if (i < NTOKEN) g_deg[i] = 0;
}

__global__ void count_kernel(const void* __restrict__ edge) {
    int is64 = g_is64;
    long long e = (long long)blockIdx.x * blockDim.x + threadIdx.x;
    if (e < NEDGE) {
        int d = (int)load_idx(edge, (long long)NEDGE + e, is64);
        atomicAdd(&g_deg[d], 1);
    }
}

__global__ void dinv_kernel() {
    int i = blockIdx.x * blockDim.x + threadIdx.x;
    if (i < NTOKEN) g_dinv[i] = rsqrtf((float)g_deg[i] + 1.0f);
}

// Single-block exclusive scan over 150000 degrees -> g_off, g_cur.
__global__ void scan_kernel() {
    __shared__ int ssum[1024];
    const int n = NTOKEN;
    int tid = threadIdx.x;
    int chunk = (n + 1023) / 1024;           // 147
    int b = tid * chunk;
    int e = min(b + chunk, n);
    int s = 0;
    for (int i = b; i < e; i++) s += g_deg[i];
    ssum[tid] = s;
    __syncthreads();
    // Hillis-Steele inclusive scan
    for (int off = 1; off < 1024; off <<= 1) {
        int v = 0;
        if (tid >= off) v = ssum[tid - off];
        __syncthreads();
        ssum[tid] += v;
        __syncthreads();
    }
    int run = (tid > 0) ? ssum[tid - 1] : 0;  // exclusive
    for (int i = b; i < e; i++) {
        g_off[i] = run;
        g_cur[i] = run;
        run += g_deg[i];
    }
}

__global__ void scatter_kernel(const void* __restrict__ edge) {
    int is64 = g_is64;
    long long e = (long long)blockIdx.x * blockDim.x + threadIdx.x;
    if (e < NEDGE) {
        int s = (int)load_idx(edge, e, is64);
        int d = (int)load_idx(edge, (long long)NEDGE + e, is64);
        int pos = atomicAdd(&g_cur[d], 1);
        g_srcs[pos] = s;
    }
}

// Layer-1: aggX[v] = dinv[v]^2 * emb[v] + sum_{s in N(v)} dinv[s]*dinv[v] * emb[s]
// One warp per node; 2 floats/lane; register accumulation, no atomics.
__global__ void agg1_kernel(const float* __restrict__ emb) {
    int w = (blockIdx.x * blockDim.x + threadIdx.x) >> 5;
    int lane = threadIdx.x & 31;
    if (w >= NTOKEN) return;
    float dv = g_dinv[w];
    const float* ev = emb + (size_t)w * 64;
    float a0 = dv * dv * ev[lane];
    float a1 = dv * dv * ev[lane + 32];
    int o = g_off[w];
    int d = g_deg[w];
    for (int j = 0; j < d; j++) {
        int s = g_srcs[o + j];
        float wt = g_dinv[s] * dv;
        const float* es = emb + (size_t)s * 64;
        a0 += wt * es[lane];
        a1 += wt * es[lane + 32];
    }
    g_aggX[(size_t)w * 64 + lane] = a0;
    g_aggX[(size_t)w * 64 + lane + 32] = a1;
}

// Wc = W1 @ W2  (64x128 @ 128x64 -> 64x64),  bc = b1 @ W2
__global__ void wc_kernel(const float* __restrict__ W1, const float* __restrict__ b1,
                          const float* __restrict__ W2) {
    int t = threadIdx.x;  // 256 threads, 1 block
    for (int idx = t; idx < 64 * 64; idx += 256) {
        int i = idx >> 6, j = idx & 63;
        float s = 0.0f;
        for (int k = 0; k < 128; k++) s += W1[i * 128 + k] * W2[k * 64 + j];
        g_Wc[idx] = s;
    }
    if (t < 64) {
        float s = 0.0f;
        for (int k = 0; k < 128; k++) s += b1[k] * W2[k * 64 + t];
        g_bc[t] = s;
    }
}

// g[v] = aggX[v] @ Wc + bc. Warp per row; Wc in smem; row broadcast via shfl.
__global__ void gmat_kernel() {
    __shared__ float sWc[64 * 64];
    __shared__ float sbc[64];
    for (int i = threadIdx.x; i < 64 * 64; i += blockDim.x) sWc[i] = g_Wc[i];
    if (threadIdx.x < 64) sbc[threadIdx.x] = g_bc[threadIdx.x];
    __syncthreads();
    int w = (blockIdx.x * blockDim.x + threadIdx.x) >> 5;
    int lane = threadIdx.x & 31;
    if (w >= NTOKEN) return;
    float x0 = g_aggX[(size_t)w * 64 + lane];
    float x1 = g_aggX[(size_t)w * 64 + lane + 32];
    float a0 = sbc[lane];
    float a1 = sbc[lane + 32];
#pragma unroll
    for (int k = 0; k < 32; k++) {
        float xk = __shfl_sync(0xffffffffu, x0, k);
        a0 += xk * sWc[k * 64 + lane];
        a1 += xk * sWc[k * 64 + lane + 32];
    }
#pragma unroll
    for (int k = 0; k < 32; k++) {
        float xk = __shfl_sync(0xffffffffu, x1, k);
        a0 += xk * sWc[(k + 32) * 64 + lane];
        a1 += xk * sWc[(k + 32) * 64 + lane + 32];
    }
    g_gv[(size_t)w * 64 + lane] = a0;
    g_gv[(size_t)w * 64 + lane + 32] = a1;
}

// Fused layer-2 aggregation + gather:
// out[pos] = dinv[v]^2 g[v] + b2 + sum_{s in N(v)} dinv[s]dinv[v] g[s], v = input[pos]
__global__ void out_kernel(const void* __restrict__ input, const float* __restrict__ b2,
                           float* __restrict__ out, int npos) {
    int is64 = g_is64;
    int w = (blockIdx.x * blockDim.x + threadIdx.x) >> 5;
    int lane = threadIdx.x & 31;
    if (w >= npos) return;
    int v = (int)load_idx(input, w, is64);
    float dv = g_dinv[v];
    const float* gv = g_gv + (size_t)v * 64;
    float a0 = dv * dv * gv[lane] + b2[lane];
    float a1 = dv * dv * gv[lane + 32] + b2[lane + 32];
    int o = g_off[v];
    int d = g_deg[v];
    for (int j = 0; j < d; j++) {
        int s = g_srcs[o + j];
        float wt = g_dinv[s] * dv;
        a0 += wt * g_gv[(size_t)s * 64 + lane];
        a1 += wt * g_gv[(size_t)s * 64 + lane + 32];
    }
    out[(size_t)w * 64 + lane] = a0;
    out[(size_t)w * 64 + lane + 32] = a1;
}

extern "C" void kernel_launch(void* const* d_in, const int* in_sizes, int n_in,
                              void* d_out, int out_size) {
    const float* emb = (const float*)d_in[0];
    const float* W1  = (const float*)d_in[1];
    const float* b1  = (const float*)d_in[2];
    const float* W2  = (const float*)d_in[3];
    const float* b2  = (const float*)d_in[4];
    const void*  input = d_in[5];
    // d_in[6] = input_timestamp (unused by reference)
    const void*  edge  = d_in[7];
    float* out = (float*)d_out;
    int npos = in_sizes[5];  // B*L = 12800

    detect_kernel<<<1, 32>>>(edge);
    zero_deg_kernel<<<(NTOKEN + 255) / 256, 256>>>();
    count_kernel<<<(NEDGE + 255) / 256, 256>>>(edge);
    dinv_kernel<<<(NTOKEN + 255) / 256, 256>>>();
    scan_kernel<<<1, 1024>>>();
    scatter_kernel<<<(NEDGE + 255) / 256, 256>>>(edge);
    wc_kernel<<<1, 256>>>(W1, b1, W2);
    agg1_kernel<<<(NTOKEN * 32 + 255) / 256, 256>>>(emb);
    gmat_kernel<<<(NTOKEN * 32 + 255) / 256, 256>>>();
    out_kernel<<<(npos * 32 + 255) / 256, 256>>>(input, b2, out, npos);
}

// round 2
// speedup vs baseline: 1.0175x; 1.0175x over previous
#include <cuda_runtime.h>
#include <cuda_bf16.h>

#define NTOKEN 150000
#define NEDGE  2400000

// ---------------- scratch (static __device__, no allocation) ----------------
__device__ int   g_is64;
__device__ int   g_deg[NTOKEN];
__device__ int   g_off[NTOKEN];
__device__ int   g_cur[NTOKEN];
__device__ float g_dinv[NTOKEN];
__device__ int   g_srcs[NEDGE];
__device__ float g_Y2[(size_t)NTOKEN * 64];   // dinv[v] * (emb[v] @ Wc)
__device__ float g_g2[(size_t)NTOKEN * 64];   // dinv[v] * h2[v]
__device__ float g_Wc[64 * 64];               // W1 @ W2
__device__ float g_bc[64];                    // b1 @ W2

// Detect int64 vs int32 indices + zero degree array (one fused launch).
__global__ void detect_zero_kernel(const void* __restrict__ edge) {
    int i = blockIdx.x * blockDim.x + threadIdx.x;
    if (i < NTOKEN) g_deg[i] = 0;
    if (blockIdx.x == 0 && threadIdx.x == 0) {
        const unsigned long long* e = (const unsigned long long*)edge;
        int is64 = 1;
        for (int k = 0; k < 64; k++)
            if ((e[k] >> 32) != 0ull) { is64 = 0; break; }
        g_is64 = is64;
    }
}

// Unified int32-view index load: for little-endian int64 with values < 2^31,
// value lives in the low word -> read ints with stride 2.
__global__ void count_kernel(const void* __restrict__ edge) {
    int st = g_is64 ? 2 : 1;
    const int* e = (const int*)edge;
    long long i = (long long)blockIdx.x * blockDim.x + threadIdx.x;
    if (i < NEDGE) {
        int d = e[((long long)NEDGE + i) * st];
        atomicAdd(&g_deg[d], 1);
    }
}

// Single-block exclusive scan over degrees; also emits dinv and cursor copy.
__global__ void scan_kernel() {
    __shared__ int ssum[1024];
    const int n = NTOKEN;
    int tid = threadIdx.x;
    int chunk = (n + 1023) / 1024;
    int b = tid * chunk;
    int e = min(b + chunk, n);
    int s = 0;
    for (int i = b; i < e; i++) s += g_deg[i];
    ssum[tid] = s;
    __syncthreads();
    for (int off = 1; off < 1024; off <<= 1) {
        int v = 0;
        if (tid >= off) v = ssum[tid - off];
        __syncthreads();
        ssum[tid] += v;
        __syncthreads();
    }
    int run = (tid > 0) ? ssum[tid - 1] : 0;
    for (int i = b; i < e; i++) {
        int d = g_deg[i];
        g_off[i] = run;
        g_cur[i] = run;
        g_dinv[i] = rsqrtf((float)d + 1.0f);
        run += d;
    }
}

__global__ void scatter_kernel(const void* __restrict__ edge) {
    int st = g_is64 ? 2 : 1;
    const int* e = (const int*)edge;
    long long i = (long long)blockIdx.x * blockDim.x + threadIdx.x;
    if (i < NEDGE) {
        int s = e[i * st];
        int d = e[((long long)NEDGE + i) * st];
        int pos = atomicAdd(&g_cur[d], 1);
        g_srcs[pos] = s;
    }
}

// Wc = W1 @ W2 (64x128 @ 128x64), bc = b1 @ W2
__global__ void wc_kernel(const float* __restrict__ W1, const float* __restrict__ b1,
                          const float* __restrict__ W2) {
    int t = threadIdx.x;  // 256 threads, 1 block
    for (int idx = t; idx < 64 * 64; idx += 256) {
        int i = idx >> 6, j = idx & 63;
        float s = 0.0f;
        for (int k = 0; k < 128; k++) s += W1[i * 128 + k] * W2[k * 64 + j];
        g_Wc[idx] = s;
    }
    if (t < 64) {
        float s = 0.0f;
        for (int k = 0; k < 128; k++) s += b1[k] * W2[k * 64 + t];
        g_bc[t] = s;
    }
}

// Y2[v] = dinv[v] * (emb[v] @ Wc). 4 nodes per warp: one smem Wc row load
// amortized over 4 nodes. Lane owns output columns {2*lane, 2*lane+1}.
__global__ void matvec_kernel(const float* __restrict__ emb) {
    __shared__ float2 sWc[64 * 32];  // row k -> float2 per lane
    for (int i = threadIdx.x; i < 64 * 32; i += blockDim.x)
        sWc[i] = ((const float2*)g_Wc)[i];
    __syncthreads();
    int warp = (blockIdx.x * blockDim.x + threadIdx.x) >> 5;
    int lane = threadIdx.x & 31;
    int vb = warp * 4;
    if (vb >= NTOKEN) return;

    float2 x[4], a[4];
#pragma unroll
    for (int n = 0; n < 4; n++) {
        int v = vb + n;
        x[n] = (v < NTOKEN) ? ((const float2*)(emb + (size_t)v * 64))[lane]
                            : make_float2(0.f, 0.f);
        a[n] = make_float2(0.f, 0.f);
    }
#pragma unroll
    for (int k = 0; k < 64; k++) {
        float2 w = sWc[k * 32 + lane];
#pragma unroll
        for (int n = 0; n < 4; n++) {
            float xk = __shfl_sync(0xffffffffu, (k & 1) ? x[n].y : x[n].x, k >> 1);
            a[n].x += xk * w.x;
            a[n].y += xk * w.y;
        }
    }
#pragma unroll
    for (int n = 0; n < 4; n++) {
        int v = vb + n;
        if (v < NTOKEN) {
            float dv = g_dinv[v];
            a[n].x *= dv; a[n].y *= dv;
            ((float2*)(g_Y2 + (size_t)v * 64))[lane] = a[n];
        }
    }
}

// g2[v] = dinv[v] * ( dinv[v]*(Y2[v] + sum_s Y2[s]) + bc ).
// Warp per node; inner loop = pure float2 adds, unrolled x4 for MLP.
__global__ void agg_kernel() {
    int v = (blockIdx.x * blockDim.x + threadIdx.x) >> 5;
    int lane = threadIdx.x & 31;
    if (v >= NTOKEN) return;
    float dv = g_dinv[v];
    float2 acc = ((const float2*)(g_Y2 + (size_t)v * 64))[lane];  // self term
    int o = g_off[v];
    int d = g_deg[v];
    int j = 0;
    for (; j + 3 < d; j += 4) {
        int s0 = g_srcs[o + j], s1 = g_srcs[o + j + 1];
        int s2 = g_srcs[o + j + 2], s3 = g_srcs[o + j + 3];
        float2 y0 = ((const float2*)(g_Y2 + (size_t)s0 * 64))[lane];
        float2 y1 = ((const float2*)(g_Y2 + (size_t)s1 * 64))[lane];
        float2 y2 = ((const float2*)(g_Y2 + (size_t)s2 * 64))[lane];
        float2 y3 = ((const float2*)(g_Y2 + (size_t)s3 * 64))[lane];
        acc.x += y0.x + y1.x + y2.x + y3.x;
        acc.y += y0.y + y1.y + y2.y + y3.y;
    }
    for (; j < d; j++) {
        int s = g_srcs[o + j];
        float2 y = ((const float2*)(g_Y2 + (size_t)s * 64))[lane];
        acc.x += y.x; acc.y += y.y;
    }
    float2 bc = ((const float2*)g_bc)[lane];
    float2 g2;
    g2.x = dv * (dv * acc.x + bc.x);
    g2.y = dv * (dv * acc.y + bc.y);
    ((float2*)(g_g2 + (size_t)v * 64))[lane] = g2;
}

// out[pos] = dinv[v]*(g2[v] + sum_s g2[s]) + b2, v = input[pos]
__global__ void out_kernel(const void* __restrict__ input, const float* __restrict__ b2,
                           float* __restrict__ out, int npos) {
    int st = g_is64 ? 2 : 1;
    const int* inp = (const int*)input;
    int w = (blockIdx.x * blockDim.x + threadIdx.x) >> 5;
    int lane = threadIdx.x & 31;
    if (w >= npos) return;
    int v = inp[(long long)w * st];
    float dv = g_dinv[v];
    float2 acc = ((const float2*)(g_g2 + (size_t)v * 64))[lane];  // self term
    int o = g_off[v];
    int d = g_deg[v];
    int j = 0;
    for (; j + 3 < d; j += 4) {
        int s0 = g_srcs[o + j], s1 = g_srcs[o + j + 1];
        int s2 = g_srcs[o + j + 2], s3 = g_srcs[o + j + 3];
        float2 y0 = ((const float2*)(g_g2 + (size_t)s0 * 64))[lane];
        float2 y1 = ((const float2*)(g_g2 + (size_t)s1 * 64))[lane];
        float2 y2 = ((const float2*)(g_g2 + (size_t)s2 * 64))[lane];
        float2 y3 = ((const float2*)(g_g2 + (size_t)s3 * 64))[lane];
        acc.x += y0.x + y1.x + y2.x + y3.x;
        acc.y += y0.y + y1.y + y2.y + y3.y;
    }
    for (; j < d; j++) {
        int s = g_srcs[o + j];
        float2 y = ((const float2*)(g_g2 + (size_t)s * 64))[lane];
        acc.x += y.x; acc.y += y.y;
    }
    float2 b = ((const float2*)b2)[lane];
    float2 r;
    r.x = dv * acc.x + b.x;
    r.y = dv * acc.y + b.y;
    ((float2*)(out + (size_t)w * 64))[lane] = r;
}

extern "C" void kernel_launch(void* const* d_in, const int* in_sizes, int n_in,
                              void* d_out, int out_size) {
    const float* emb = (const float*)d_in[0];
    const float* W1  = (const float*)d_in[1];
    const float* b1  = (const float*)d_in[2];
    const float* W2  = (const float*)d_in[3];
    const float* b2  = (const float*)d_in[4];
    const void*  input = d_in[5];
    const void*  edge  = d_in[7];
    float* out = (float*)d_out;
    int npos = in_sizes[5];  // B*L = 12800

    detect_zero_kernel<<<(NTOKEN + 255) / 256, 256>>>(edge);
    count_kernel<<<(NEDGE + 255) / 256, 256>>>(edge);
    scan_kernel<<<1, 1024>>>();
    scatter_kernel<<<(NEDGE + 255) / 256, 256>>>(edge);
    wc_kernel<<<1, 256>>>(W1, b1, W2);
    matvec_kernel<<<((NTOKEN + 3) / 4 * 32 + 255) / 256, 256>>>(emb);
    agg_kernel<<<(NTOKEN * 32 + 255) / 256, 256>>>();
    out_kernel<<<(npos * 32 + 255) / 256, 256>>>(input, b2, out, npos);
}

// round 3
// speedup vs baseline: 2.3469x; 2.3065x over previous
#include <cuda_runtime.h>
#include <cuda_bf16.h>

#define NTOKEN 150000
#define NEDGE  2400000
#define NSCANB ((NTOKEN + 255) / 256)   // 586 scan tiles

// ---------------- scratch (static __device__, no allocation) ----------------
__device__ int   g_is64;
__device__ int   g_deg[NTOKEN];
__device__ int   g_off[NTOKEN];
__device__ int   g_cur[NTOKEN];
__device__ float g_dinv[NTOKEN];
__device__ int   g_srcs[NEDGE];
__device__ float g_Y2[(size_t)NTOKEN * 64];   // dinv[v] * (emb[v] @ Wc)
__device__ float g_g2[(size_t)NTOKEN * 64];   // dinv[v] * h2[v]
__device__ float g_Wc[64 * 64];               // W1 @ W2
__device__ float g_bc[64];                    // b1 @ W2
__device__ int   g_bsum[NSCANB];              // per-tile degree sums
__device__ int   g_boff[NSCANB];              // exclusive tile offsets

// Detect int64 vs int32 indices + zero degree array (one fused launch).
__global__ void detect_zero_kernel(const void* __restrict__ edge) {
    int i = blockIdx.x * blockDim.x + threadIdx.x;
    if (i < NTOKEN) g_deg[i] = 0;
    if (blockIdx.x == 0 && threadIdx.x == 0) {
        const unsigned long long* e = (const unsigned long long*)edge;
        int is64 = 1;
        for (int k = 0; k < 64; k++)
            if ((e[k] >> 32) != 0ull) { is64 = 0; break; }
        g_is64 = is64;
    }
}

// Unified int32-view index load: little-endian int64 with values < 2^31
// keeps the value in the low word -> read ints with stride 2.
__global__ void count_kernel(const void* __restrict__ edge) {
    int st = g_is64 ? 2 : 1;
    const int* e = (const int*)edge;
    long long i = (long long)blockIdx.x * blockDim.x + threadIdx.x;
    if (i < NEDGE) {
        int d = e[((long long)NEDGE + i) * st];
        atomicAdd(&g_deg[d], 1);
    }
}

// ---- 3-phase coalesced exclusive scan over g_deg ----
__global__ void scan1_kernel() {   // per-tile sums
    __shared__ int sh[256];
    int t = threadIdx.x;
    int i = blockIdx.x * 256 + t;
    int d = (i < NTOKEN) ? g_deg[i] : 0;
    sh[t] = d;
    __syncthreads();
    for (int off = 128; off > 0; off >>= 1) {
        if (t < off) sh[t] += sh[t + off];
        __syncthreads();
    }
    if (t == 0) g_bsum[blockIdx.x] = sh[0];
}

__global__ void scan2_kernel() {   // scan the 586 tile sums (1 block)
    __shared__ int sh[1024];
    int t = threadIdx.x;
    int v = (t < NSCANB) ? g_bsum[t] : 0;
    sh[t] = v;
    __syncthreads();
    for (int off = 1; off < 1024; off <<= 1) {
        int u = (t >= off) ? sh[t - off] : 0;
        __syncthreads();
        sh[t] += u;
        __syncthreads();
    }
    if (t < NSCANB) g_boff[t] = sh[t] - v;   // exclusive
}

__global__ void scan3_kernel() {   // per-tile exclusive scan + emit off/cur/dinv
    __shared__ int sh[256];
    int t = threadIdx.x;
    int i = blockIdx.x * 256 + t;
    int d = (i < NTOKEN) ? g_deg[i] : 0;
    sh[t] = d;
    __syncthreads();
    for (int off = 1; off < 256; off <<= 1) {
        int u = (t >= off) ? sh[t - off] : 0;
        __syncthreads();
        sh[t] += u;
        __syncthreads();
    }
    if (i < NTOKEN) {
        int excl = sh[t] - d + g_boff[blockIdx.x];
        g_off[i] = excl;
        g_cur[i] = excl;
        g_dinv[i] = rsqrtf((float)d + 1.0f);
    }
}

__global__ void scatter_kernel(const void* __restrict__ edge) {
    int st = g_is64 ? 2 : 1;
    const int* e = (const int*)edge;
    long long i = (long long)blockIdx.x * blockDim.x + threadIdx.x;
    if (i < NEDGE) {
        int s = e[i * st];
        int d = e[((long long)NEDGE + i) * st];
        int pos = atomicAdd(&g_cur[d], 1);
        g_srcs[pos] = s;
    }
}

// Wc = W1 @ W2 (64x128 @ 128x64), bc = b1 @ W2
__global__ void wc_kernel(const float* __restrict__ W1, const float* __restrict__ b1,
                          const float* __restrict__ W2) {
    int t = threadIdx.x;  // 256 threads, 1 block
    for (int idx = t; idx < 64 * 64; idx += 256) {
        int i = idx >> 6, j = idx & 63;
        float s = 0.0f;
        for (int k = 0; k < 128; k++) s += W1[i * 128 + k] * W2[k * 64 + j];
        g_Wc[idx] = s;
    }
    if (t < 64) {
        float s = 0.0f;
        for (int k = 0; k < 128; k++) s += b1[k] * W2[k * 64 + t];
        g_bc[t] = s;
    }
}

// Y2[v] = dinv[v] * (emb[v] @ Wc). 4 nodes per warp; Wc row load amortized.
__global__ void matvec_kernel(const float* __restrict__ emb) {
    __shared__ float2 sWc[64 * 32];
    for (int i = threadIdx.x; i < 64 * 32; i += blockDim.x)
        sWc[i] = ((const float2*)g_Wc)[i];
    __syncthreads();
    int warp = (blockIdx.x * blockDim.x + threadIdx.x) >> 5;
    int lane = threadIdx.x & 31;
    int vb = warp * 4;
    if (vb >= NTOKEN) return;

    float2 x[4], a[4];
#pragma unroll
    for (int n = 0; n < 4; n++) {
        int v = vb + n;
        x[n] = (v < NTOKEN) ? ((const float2*)(emb + (size_t)v * 64))[lane]
                            : make_float2(0.f, 0.f);
        a[n] = make_float2(0.f, 0.f);
    }
#pragma unroll
    for (int k = 0; k < 64; k++) {
        float2 w = sWc[k * 32 + lane];
#pragma unroll
        for (int n = 0; n < 4; n++) {
            float xk = __shfl_sync(0xffffffffu, (k & 1) ? x[n].y : x[n].x, k >> 1);
            a[n].x += xk * w.x;
            a[n].y += xk * w.y;
        }
    }
#pragma unroll
    for (int n = 0; n < 4; n++) {
        int v = vb + n;
        if (v < NTOKEN) {
            float dv = g_dinv[v];
            a[n].x *= dv; a[n].y *= dv;
            ((float2*)(g_Y2 + (size_t)v * 64))[lane] = a[n];
        }
    }
}

// g2[v] = dinv[v] * ( dinv[v]*(Y2[v] + sum_s Y2[s]) + bc ).
__global__ void agg_kernel() {
    int v = (blockIdx.x * blockDim.x + threadIdx.x) >> 5;
    int lane = threadIdx.x & 31;
    if (v >= NTOKEN) return;
    float dv = g_dinv[v];
    float2 acc = ((const float2*)(g_Y2 + (size_t)v * 64))[lane];  // self term
    int o = g_off[v];
    int d = g_deg[v];
    int j = 0;
    for (; j + 3 < d; j += 4) {
        int s0 = g_srcs[o + j], s1 = g_srcs[o + j + 1];
        int s2 = g_srcs[o + j + 2], s3 = g_srcs[o + j + 3];
        float2 y0 = ((const float2*)(g_Y2 + (size_t)s0 * 64))[lane];
        float2 y1 = ((const float2*)(g_Y2 + (size_t)s1 * 64))[lane];
        float2 y2 = ((const float2*)(g_Y2 + (size_t)s2 * 64))[lane];
        float2 y3 = ((const float2*)(g_Y2 + (size_t)s3 * 64))[lane];
        acc.x += y0.x + y1.x + y2.x + y3.x;
        acc.y += y0.y + y1.y + y2.y + y3.y;
    }
    for (; j < d; j++) {
        int s = g_srcs[o + j];
        float2 y = ((const float2*)(g_Y2 + (size_t)s * 64))[lane];
        acc.x += y.x; acc.y += y.y;
    }
    float2 bc = ((const float2*)g_bc)[lane];
    float2 g2;
    g2.x = dv * (dv * acc.x + bc.x);
    g2.y = dv * (dv * acc.y + bc.y);
    ((float2*)(g_g2 + (size_t)v * 64))[lane] = g2;
}

// out[pos] = dinv[v]*(g2[v] + sum_s g2[s]) + b2, v = input[pos]
__global__ void out_kernel(const void* __restrict__ input, const float* __restrict__ b2,
                           float* __restrict__ out, int npos) {
    int st = g_is64 ? 2 : 1;
    const int* inp = (const int*)input;
    int w = (blockIdx.x * blockDim.x + threadIdx.x) >> 5;
    int lane = threadIdx.x & 31;
    if (w >= npos) return;
    int v = inp[(long long)w * st];
    float dv = g_dinv[v];
    float2 acc = ((const float2*)(g_g2 + (size_t)v * 64))[lane];  // self term
    int o = g_off[v];
    int d = g_deg[v];
    int j = 0;
    for (; j + 3 < d; j += 4) {
        int s0 = g_srcs[o + j], s1 = g_srcs[o + j + 1];
        int s2 = g_srcs[o + j + 2], s3 = g_srcs[o + j + 3];
        float2 y0 = ((const float2*)(g_g2 + (size_t)s0 * 64))[lane];
        float2 y1 = ((const float2*)(g_g2 + (size_t)s1 * 64))[lane];
        float2 y2 = ((const float2*)(g_g2 + (size_t)s2 * 64))[lane];
        float2 y3 = ((const float2*)(g_g2 + (size_t)s3 * 64))[lane];
        acc.x += y0.x + y1.x + y2.x + y3.x;
        acc.y += y0.y + y1.y + y2.y + y3.y;
    }
    for (; j < d; j++) {
        int s = g_srcs[o + j];
        float2 y = ((const float2*)(g_g2 + (size_t)s * 64))[lane];
        acc.x += y.x; acc.y += y.y;
    }
    float2 b = ((const float2*)b2)[lane];
    float2 r;
    r.x = dv * acc.x + b.x;
    r.y = dv * acc.y + b.y;
    ((float2*)(out + (size_t)w * 64))[lane] = r;
}

extern "C" void kernel_launch(void* const* d_in, const int* in_sizes, int n_in,
                              void* d_out, int out_size) {
    const float* emb = (const float*)d_in[0];
    const float* W1  = (const float*)d_in[1];
    const float* b1  = (const float*)d_in[2];
    const float* W2  = (const float*)d_in[3];
    const float* b2  = (const float*)d_in[4];
    const void*  input = d_in[5];
    const void*  edge  = d_in[7];
    float* out = (float*)d_out;
    int npos = in_sizes[5];  // B*L = 12800

    detect_zero_kernel<<<(NTOKEN + 255) / 256, 256>>>(edge);
    count_kernel<<<(NEDGE + 255) / 256, 256>>>(edge);
    scan1_kernel<<<NSCANB, 256>>>();
    scan2_kernel<<<1, 1024>>>();
    scan3_kernel<<<NSCANB, 256>>>();
    scatter_kernel<<<(NEDGE + 255) / 256, 256>>>(edge);
    wc_kernel<<<1, 256>>>(W1, b1, W2);
    matvec_kernel<<<((NTOKEN + 3) / 4 * 32 + 255) / 256, 256>>>(emb);
    agg_kernel<<<(NTOKEN * 32 + 255) / 256, 256>>>();
    out_kernel<<<(npos * 32 + 255) / 256, 256>>>(input, b2, out, npos);
}

// round 4
// speedup vs baseline: 2.5750x; 1.0972x over previous
#include <cuda_runtime.h>
#include <cuda_bf16.h>

#define NTOKEN 150000
#define NEDGE  2400000
#define NSCANB ((NTOKEN + 255) / 256)   // 586 scan tiles

// ---------------- scratch (static __device__, no allocation) ----------------
__device__ int   g_is64;
__device__ int   g_deg[NTOKEN];
__device__ int   g_off[NTOKEN];
__device__ int   g_cur[NTOKEN];
__device__ float g_dinv[NTOKEN];
__device__ int   g_srcs[NEDGE];
__device__ float g_Y2[(size_t)NTOKEN * 64];   // dinv[v] * (emb[v] @ Wc)
__device__ float g_g2[(size_t)NTOKEN * 64];   // dinv[v] * h2[v]
__device__ float g_Wc[64 * 64];               // W1 @ W2
__device__ float g_bc[64];                    // b1 @ W2
__device__ int   g_bsum[NSCANB];              // per-tile degree sums
__device__ int   g_boff[NSCANB];              // exclusive tile offsets

// Detect int64 vs int32 indices + zero degree array (one fused launch).
__global__ void detect_zero_kernel(const void* __restrict__ edge) {
    int i = blockIdx.x * blockDim.x + threadIdx.x;
    if (i < NTOKEN) g_deg[i] = 0;
    if (blockIdx.x == 0 && threadIdx.x == 0) {
        const unsigned long long* e = (const unsigned long long*)edge;
        int is64 = 1;
        for (int k = 0; k < 64; k++)
            if ((e[k] >> 32) != 0ull) { is64 = 0; break; }
        g_is64 = is64;
    }
}

// int32-view index load: little-endian int64 with values < 2^31 keeps the
// value in the low word -> read ints with stride 2.
__global__ void count_kernel(const void* __restrict__ edge) {
    int st = g_is64 ? 2 : 1;
    const int* e = (const int*)edge;
    long long i = (long long)blockIdx.x * blockDim.x + threadIdx.x;
    if (i < NEDGE) {
        int d = e[((long long)NEDGE + i) * st];
        atomicAdd(&g_deg[d], 1);
    }
}

// ---- 3-phase coalesced exclusive scan over g_deg ----
// scan1 also emits dinv so the dense chain (matvec) can fork right after it.
__global__ void scan1_kernel() {
    __shared__ int sh[256];
    int t = threadIdx.x;
    int i = blockIdx.x * 256 + t;
    int d = (i < NTOKEN) ? g_deg[i] : 0;
    if (i < NTOKEN) g_dinv[i] = rsqrtf((float)d + 1.0f);
    sh[t] = d;
    __syncthreads();
    for (int off = 128; off > 0; off >>= 1) {
        if (t < off) sh[t] += sh[t + off];
        __syncthreads();
    }
    if (t == 0) g_bsum[blockIdx.x] = sh[0];
}

__global__ void scan2_kernel() {   // scan the 586 tile sums (1 block)
    __shared__ int sh[1024];
    int t = threadIdx.x;
    int v = (t < NSCANB) ? g_bsum[t] : 0;
    sh[t] = v;
    __syncthreads();
    for (int off = 1; off < 1024; off <<= 1) {
        int u = (t >= off) ? sh[t - off] : 0;
        __syncthreads();
        sh[t] += u;
        __syncthreads();
    }
    if (t < NSCANB) g_boff[t] = sh[t] - v;   // exclusive
}

__global__ void scan3_kernel() {   // per-tile exclusive scan + emit off/cur
    __shared__ int sh[256];
    int t = threadIdx.x;
    int i = blockIdx.x * 256 + t;
    int d = (i < NTOKEN) ? g_deg[i] : 0;
    sh[t] = d;
    __syncthreads();
    for (int off = 1; off < 256; off <<= 1) {
        int u = (t >= off) ? sh[t - off] : 0;
        __syncthreads();
        sh[t] += u;
        __syncthreads();
    }
    if (i < NTOKEN) {
        int excl = sh[t] - d + g_boff[blockIdx.x];
        g_off[i] = excl;
        g_cur[i] = excl;
    }
}

__global__ void scatter_kernel(const void* __restrict__ edge) {
    int st = g_is64 ? 2 : 1;
    const int* e = (const int*)edge;
    long long i = (long long)blockIdx.x * blockDim.x + threadIdx.x;
    if (i < NEDGE) {
        int s = e[i * st];
        int d = e[((long long)NEDGE + i) * st];
        int pos = atomicAdd(&g_cur[d], 1);
        g_srcs[pos] = s;
    }
}

// Wc = W1 @ W2 (64x128 @ 128x64), bc = b1 @ W2
__global__ void wc_kernel(const float* __restrict__ W1, const float* __restrict__ b1,
                          const float* __restrict__ W2) {
    int t = threadIdx.x;  // 256 threads, 1 block
    for (int idx = t; idx < 64 * 64; idx += 256) {
        int i = idx >> 6, j = idx & 63;
        float s = 0.0f;
        for (int k = 0; k < 128; k++) s += W1[i * 128 + k] * W2[k * 64 + j];
        g_Wc[idx] = s;
    }
    if (t < 64) {
        float s = 0.0f;
        for (int k = 0; k < 128; k++) s += b1[k] * W2[k * 64 + t];
        g_bc[t] = s;
    }
}

// Y2[v] = dinv[v] * (emb[v] @ Wc). 4 nodes per warp; Wc row load amortized.
__global__ void matvec_kernel(const float* __restrict__ emb) {
    __shared__ float2 sWc[64 * 32];
    for (int i = threadIdx.x; i < 64 * 32; i += blockDim.x)
        sWc[i] = ((const float2*)g_Wc)[i];
    __syncthreads();
    int warp = (blockIdx.x * blockDim.x + threadIdx.x) >> 5;
    int lane = threadIdx.x & 31;
    int vb = warp * 4;
    if (vb >= NTOKEN) return;

    float2 x[4], a[4];
#pragma unroll
    for (int n = 0; n < 4; n++) {
        int v = vb + n;
        x[n] = (v < NTOKEN) ? ((const float2*)(emb + (size_t)v * 64))[lane]
                            : make_float2(0.f, 0.f);
        a[n] = make_float2(0.f, 0.f);
    }
#pragma unroll
    for (int k = 0; k < 64; k++) {
        float2 w = sWc[k * 32 + lane];
#pragma unroll
        for (int n = 0; n < 4; n++) {
            float xk = __shfl_sync(0xffffffffu, (k & 1) ? x[n].y : x[n].x, k >> 1);
            a[n].x += xk * w.x;
            a[n].y += xk * w.y;
        }
    }
#pragma unroll
    for (int n = 0; n < 4; n++) {
        int v = vb + n;
        if (v < NTOKEN) {
            float dv = g_dinv[v];
            a[n].x *= dv; a[n].y *= dv;
            ((float2*)(g_Y2 + (size_t)v * 64))[lane] = a[n];
        }
    }
}

// g2[v] = dinv[v] * ( dinv[v]*(Y2[v] + sum_s Y2[s]) + bc ).
__global__ void agg_kernel() {
    int v = (blockIdx.x * blockDim.x + threadIdx.x) >> 5;
    int lane = threadIdx.x & 31;
    if (v >= NTOKEN) return;
    float dv = g_dinv[v];
    float2 acc = ((const float2*)(g_Y2 + (size_t)v * 64))[lane];  // self term
    int o = g_off[v];
    int d = g_deg[v];
    int j = 0;
    for (; j + 3 < d; j += 4) {
        int s0 = g_srcs[o + j], s1 = g_srcs[o + j + 1];
        int s2 = g_srcs[o + j + 2], s3 = g_srcs[o + j + 3];
        float2 y0 = ((const float2*)(g_Y2 + (size_t)s0 * 64))[lane];
        float2 y1 = ((const float2*)(g_Y2 + (size_t)s1 * 64))[lane];
        float2 y2 = ((const float2*)(g_Y2 + (size_t)s2 * 64))[lane];
        float2 y3 = ((const float2*)(g_Y2 + (size_t)s3 * 64))[lane];
        acc.x += y0.x + y1.x + y2.x + y3.x;
        acc.y += y0.y + y1.y + y2.y + y3.y;
    }
    for (; j < d; j++) {
        int s = g_srcs[o + j];
        float2 y = ((const float2*)(g_Y2 + (size_t)s * 64))[lane];
        acc.x += y.x; acc.y += y.y;
    }
    float2 bc = ((const float2*)g_bc)[lane];
    float2 g2;
    g2.x = dv * (dv * acc.x + bc.x);
    g2.y = dv * (dv * acc.y + bc.y);
    ((float2*)(g_g2 + (size_t)v * 64))[lane] = g2;
}

// out[pos] = dinv[v]*(g2[v] + sum_s g2[s]) + b2, v = input[pos]
__global__ void out_kernel(const void* __restrict__ input, const float* __restrict__ b2,
                           float* __restrict__ out, int npos) {
    int st = g_is64 ? 2 : 1;
    const int* inp = (const int*)input;
    int w = (blockIdx.x * blockDim.x + threadIdx.x) >> 5;
    int lane = threadIdx.x & 31;
    if (w >= npos) return;
    int v = inp[(long long)w * st];
    float dv = g_dinv[v];
    float2 acc = ((const float2*)(g_g2 + (size_t)v * 64))[lane];  // self term
    int o = g_off[v];
    int d = g_deg[v];
    int j = 0;
    for (; j + 3 < d; j += 4) {
        int s0 = g_srcs[o + j], s1 = g_srcs[o + j + 1];
        int s2 = g_srcs[o + j + 2], s3 = g_srcs[o + j + 3];
        float2 y0 = ((const float2*)(g_g2 + (size_t)s0 * 64))[lane];
        float2 y1 = ((const float2*)(g_g2 + (size_t)s1 * 64))[lane];
        float2 y2 = ((const float2*)(g_g2 + (size_t)s2 * 64))[lane];
        float2 y3 = ((const float2*)(g_g2 + (size_t)s3 * 64))[lane];
        acc.x += y0.x + y1.x + y2.x + y3.x;
        acc.y += y0.y + y1.y + y2.y + y3.y;
    }
    for (; j < d; j++) {
        int s = g_srcs[o + j];
        float2 y = ((const float2*)(g_g2 + (size_t)s * 64))[lane];
        acc.x += y.x; acc.y += y.y;
    }
    float2 b = ((const float2*)b2)[lane];
    float2 r;
    r.x = dv * acc.x + b.x;
    r.y = dv * acc.y + b.y;
    ((float2*)(out + (size_t)w * 64))[lane] = r;
}

extern "C" void kernel_launch(void* const* d_in, const int* in_sizes, int n_in,
                              void* d_out, int out_size) {
    const float* emb = (const float*)d_in[0];
    const float* W1  = (const float*)d_in[1];
    const float* b1  = (const float*)d_in[2];
    const float* W2  = (const float*)d_in[3];
    const float* b2  = (const float*)d_in[4];
    const void*  input = d_in[5];
    const void*  edge  = d_in[7];
    float* out = (float*)d_out;
    int npos = in_sizes[5];  // B*L = 12800

    // Lazily created host-side resources (first call is the uncaptured
    // correctness run; the captured call reuses them -> identical graph work).
    static cudaStream_t s1 = nullptr;
    static cudaEvent_t ev0 = nullptr, ev1 = nullptr, ev2 = nullptr;
    if (!s1) {
        cudaStreamCreateWithFlags(&s1, cudaStreamNonBlocking);
        cudaEventCreateWithFlags(&ev0, cudaEventDisableTiming);
        cudaEventCreateWithFlags(&ev1, cudaEventDisableTiming);
        cudaEventCreateWithFlags(&ev2, cudaEventDisableTiming);
    }

    // main chain (legacy stream): detect -> count -> scan1(+dinv)
    detect_zero_kernel<<<(NTOKEN + 255) / 256, 256>>>(edge);
    cudaEventRecord(ev0, 0);                 // fork point for wc
    count_kernel<<<(NEDGE + 255) / 256, 256>>>(edge);
    scan1_kernel<<<NSCANB, 256>>>();
    cudaEventRecord(ev1, 0);                 // dinv ready

    // dense side chain: wc (independent) then matvec (needs dinv + Wc)
    cudaStreamWaitEvent(s1, ev0, 0);
    wc_kernel<<<1, 256, 0, s1>>>(W1, b1, W2);
    cudaStreamWaitEvent(s1, ev1, 0);
    matvec_kernel<<<((NTOKEN + 3) / 4 * 32 + 255) / 256, 256, 0, s1>>>(emb);
    cudaEventRecord(ev2, s1);

    // main chain continues: scan2 -> scan3 -> scatter (overlaps matvec)
    scan2_kernel<<<1, 1024>>>();
    scan3_kernel<<<NSCANB, 256>>>();
    scatter_kernel<<<(NEDGE + 255) / 256, 256>>>(edge);

    // join, then aggregate + output
    cudaStreamWaitEvent(0, ev2, 0);
    agg_kernel<<<(NTOKEN * 32 + 255) / 256, 256>>>();
    out_kernel<<<(npos * 32 + 255) / 256, 256>>>(input, b2, out, npos);
}

// round 6
// speedup vs baseline: 3.3070x; 1.2843x over previous
#include <cuda_runtime.h>
#include <cuda_bf16.h>

#define NTOKEN 150000
#define NEDGE  2400000
#define NSCANB ((NTOKEN + 255) / 256)   // 586 scan tiles

// ---------------- scratch (static __device__, no allocation) ----------------
__device__ int   g_is64;
__device__ int   g_deg[NTOKEN];
__device__ int   g_off[NTOKEN];
__device__ int   g_cur[NTOKEN];
__device__ float g_dinv[NTOKEN];
__device__ int   g_srcs[NEDGE];
__device__ float g_Y2[(size_t)NTOKEN * 64];   // dinv[v] * (emb[v] @ Wc)
__device__ float g_g2[(size_t)NTOKEN * 64];   // dinv[v] * h2[v]
__device__ float g_Wc[64 * 64];               // W1 @ W2
__device__ float g_bc[64];                    // b1 @ W2
__device__ int   g_bsum[NSCANB];              // per-tile degree sums
__device__ int   g_boff[NSCANB];              // exclusive tile offsets

// Detect int64 vs int32 indices + zero degree array (one fused launch).
__global__ void detect_zero_kernel(const void* __restrict__ edge) {
    int i = blockIdx.x * blockDim.x + threadIdx.x;
    if (i < NTOKEN) g_deg[i] = 0;
    if (blockIdx.x == 0 && threadIdx.x == 0) {
        const unsigned long long* e = (const unsigned long long*)edge;
        int is64 = 1;
        for (int k = 0; k < 64; k++)
            if ((e[k] >> 32) != 0ull) { is64 = 0; break; }
        g_is64 = is64;
    }
}

// int32-view index load: little-endian int64 with values < 2^31 keeps the
// value in the low word -> read ints with stride 2.
__global__ void count_kernel(const void* __restrict__ edge) {
    int st = g_is64 ? 2 : 1;
    const int* e = (const int*)edge;
    long long i = (long long)blockIdx.x * blockDim.x + threadIdx.x;
    if (i < NEDGE) {
        int d = e[((long long)NEDGE + i) * st];
        atomicAdd(&g_deg[d], 1);
    }
}

// ---- 3-phase coalesced exclusive scan over g_deg ----
// scan1 also emits dinv so the dense chain (matvec) can fork right after it.
__global__ void scan1_kernel() {
    __shared__ int sh[256];
    int t = threadIdx.x;
    int i = blockIdx.x * 256 + t;
    int d = (i < NTOKEN) ? g_deg[i] : 0;
    if (i < NTOKEN) g_dinv[i] = rsqrtf((float)d + 1.0f);
    sh[t] = d;
    __syncthreads();
    for (int off = 128; off > 0; off >>= 1) {
        if (t < off) sh[t] += sh[t + off];
        __syncthreads();
    }
    if (t == 0) g_bsum[blockIdx.x] = sh[0];
}

__global__ void scan2_kernel() {   // scan the 586 tile sums (1 block)
    __shared__ int sh[1024];
    int t = threadIdx.x;
    int v = (t < NSCANB) ? g_bsum[t] : 0;
    sh[t] = v;
    __syncthreads();
    for (int off = 1; off < 1024; off <<= 1) {
        int u = (t >= off) ? sh[t - off] : 0;
        __syncthreads();
        sh[t] += u;
        __syncthreads();
    }
    if (t < NSCANB) g_boff[t] = sh[t] - v;   // exclusive
}

__global__ void scan3_kernel() {   // per-tile exclusive scan + emit off/cur
    __shared__ int sh[256];
    int t = threadIdx.x;
    int i = blockIdx.x * 256 + t;
    int d = (i < NTOKEN) ? g_deg[i] : 0;
    sh[t] = d;
    __syncthreads();
    for (int off = 1; off < 256; off <<= 1) {
        int u = (t >= off) ? sh[t - off] : 0;
        __syncthreads();
        sh[t] += u;
        __syncthreads();
    }
    if (i < NTOKEN) {
        int excl = sh[t] - d + g_boff[blockIdx.x];
        g_off[i] = excl;
        g_cur[i] = excl;
    }
}

__global__ void scatter_kernel(const void* __restrict__ edge) {
    int st = g_is64 ? 2 : 1;
    const int* e = (const int*)edge;
    long long i = (long long)blockIdx.x * blockDim.x + threadIdx.x;
    if (i < NEDGE) {
        int s = e[i * st];
        int d = e[((long long)NEDGE + i) * st];
        int pos = atomicAdd(&g_cur[d], 1);
        g_srcs[pos] = s;
    }
}

// Wc = W1 @ W2 (64x128 @ 128x64), bc = b1 @ W2. 16 blocks, one elem/thread.
// W1 reads broadcast within a warp (same row), W2 reads coalesced.
__global__ void wc_kernel(const float* __restrict__ W1, const float* __restrict__ b1,
                          const float* __restrict__ W2) {
    int idx = blockIdx.x * 256 + threadIdx.x;   // 0..4095
    int i = idx >> 6, j = idx & 63;
    float s = 0.0f;
#pragma unroll 8
    for (int k = 0; k < 128; k++) s += W1[i * 128 + k] * W2[k * 64 + j];
    g_Wc[idx] = s;
    if (blockIdx.x == 0 && threadIdx.x < 64) {
        int t = threadIdx.x;
        float b = 0.0f;
#pragma unroll 8
        for (int k = 0; k < 128; k++) b += b1[k] * W2[k * 64 + t];
        g_bc[t] = b;
    }
}

// Y2[v] = dinv[v] * (emb[v] @ Wc). 4 nodes per warp; Wc row load amortized.
__global__ void matvec_kernel(const float* __restrict__ emb) {
    __shared__ float2 sWc[64 * 32];
    for (int i = threadIdx.x; i < 64 * 32; i += blockDim.x)
        sWc[i] = ((const float2*)g_Wc)[i];
    __syncthreads();
    int warp = (blockIdx.x * blockDim.x + threadIdx.x) >> 5;
    int lane = threadIdx.x & 31;
    int vb = warp * 4;
    if (vb >= NTOKEN) return;

    float2 x[4], a[4];
#pragma unroll
    for (int n = 0; n < 4; n++) {
        int v = vb + n;
        x[n] = (v < NTOKEN) ? ((const float2*)(emb + (size_t)v * 64))[lane]
                            : make_float2(0.f, 0.f);
        a[n] = make_float2(0.f, 0.f);
    }
#pragma unroll
    for (int k = 0; k < 64; k++) {
        float2 w = sWc[k * 32 + lane];
#pragma unroll
        for (int n = 0; n < 4; n++) {
            float xk = __shfl_sync(0xffffffffu, (k & 1) ? x[n].y : x[n].x, k >> 1);
            a[n].x += xk * w.x;
            a[n].y += xk * w.y;
        }
    }
#pragma unroll
    for (int n = 0; n < 4; n++) {
        int v = vb + n;
        if (v < NTOKEN) {
            float dv = g_dinv[v];
            a[n].x *= dv; a[n].y *= dv;
            ((float2*)(g_Y2 + (size_t)v * 64))[lane] = a[n];
        }
    }
}

// g2[v] = dinv[v] * ( dinv[v]*(Y2[v] + sum_s Y2[s]) + bc ).
__global__ void agg_kernel() {
    int v = (blockIdx.x * blockDim.x + threadIdx.x) >> 5;
    int lane = threadIdx.x & 31;
    if (v >= NTOKEN) return;
    float dv = g_dinv[v];
    float2 acc = ((const float2*)(g_Y2 + (size_t)v * 64))[lane];  // self term
    int o = g_off[v];
    int d = g_deg[v];
    int j = 0;
    for (; j + 3 < d; j += 4) {
        int s0 = g_srcs[o + j], s1 = g_srcs[o + j + 1];
        int s2 = g_srcs[o + j + 2], s3 = g_srcs[o + j + 3];
        float2 y0 = ((const float2*)(g_Y2 + (size_t)s0 * 64))[lane];
        float2 y1 = ((const float2*)(g_Y2 + (size_t)s1 * 64))[lane];
        float2 y2 = ((const float2*)(g_Y2 + (size_t)s2 * 64))[lane];
        float2 y3 = ((const float2*)(g_Y2 + (size_t)s3 * 64))[lane];
        acc.x += y0.x + y1.x + y2.x + y3.x;
        acc.y += y0.y + y1.y + y2.y + y3.y;
    }
    for (; j < d; j++) {
        int s = g_srcs[o + j];
        float2 y = ((const float2*)(g_Y2 + (size_t)s * 64))[lane];
        acc.x += y.x; acc.y += y.y;
    }
    float2 bc = ((const float2*)g_bc)[lane];
    float2 g2;
    g2.x = dv * (dv * acc.x + bc.x);
    g2.y = dv * (dv * acc.y + bc.y);
    ((float2*)(g_g2 + (size_t)v * 64))[lane] = g2;
}

// out[pos] = dinv[v]*(g2[v] + sum_s g2[s]) + b2, v = input[pos]
__global__ void out_kernel(const void* __restrict__ input, const float* __restrict__ b2,
                           float* __restrict__ out, int npos) {
    int st = g_is64 ? 2 : 1;
    const int* inp = (const int*)input;
    int w = (blockIdx.x * blockDim.x + threadIdx.x) >> 5;
    int lane = threadIdx.x & 31;
    if (w >= npos) return;
    int v = inp[(long long)w * st];
    float dv = g_dinv[v];
    float2 acc = ((const float2*)(g_g2 + (size_t)v * 64))[lane];  // self term
    int o = g_off[v];
    int d = g_deg[v];
    int j = 0;
    for (; j + 3 < d; j += 4) {
        int s0 = g_srcs[o + j], s1 = g_srcs[o + j + 1];
        int s2 = g_srcs[o + j + 2], s3 = g_srcs[o + j + 3];
        float2 y0 = ((const float2*)(g_g2 + (size_t)s0 * 64))[lane];
        float2 y1 = ((const float2*)(g_g2 + (size_t)s1 * 64))[lane];
        float2 y2 = ((const float2*)(g_g2 + (size_t)s2 * 64))[lane];
        float2 y3 = ((const float2*)(g_g2 + (size_t)s3 * 64))[lane];
        acc.x += y0.x + y1.x + y2.x + y3.x;
        acc.y += y0.y + y1.y + y2.y + y3.y;
    }
    for (; j < d; j++) {
        int s = g_srcs[o + j];
        float2 y = ((const float2*)(g_g2 + (size_t)s * 64))[lane];
        acc.x += y.x; acc.y += y.y;
    }
    float2 b = ((const float2*)b2)[lane];
    float2 r;
    r.x = dv * acc.x + b.x;
    r.y = dv * acc.y + b.y;
    ((float2*)(out + (size_t)w * 64))[lane] = r;
}

extern "C" void kernel_launch(void* const* d_in, const int* in_sizes, int n_in,
                              void* d_out, int out_size) {
    const float* emb = (const float*)d_in[0];
    const float* W1  = (const float*)d_in[1];
    const float* b1  = (const float*)d_in[2];
    const float* W2  = (const float*)d_in[3];
    const float* b2  = (const float*)d_in[4];
    const void*  input = d_in[5];
    const void*  edge  = d_in[7];
    float* out = (float*)d_out;
    int npos = in_sizes[5];  // B*L = 12800

    static cudaStream_t s1 = nullptr;
    static cudaEvent_t ev1 = nullptr, ev2 = nullptr;
    if (!s1) {
        cudaStreamCreateWithFlags(&s1, cudaStreamNonBlocking);
        cudaEventCreateWithFlags(&ev1, cudaEventDisableTiming);
        cudaEventCreateWithFlags(&ev2, cudaEventDisableTiming);
    }

    // dense side chain starts immediately: wc depends only on W1/b1/W2
    wc_kernel<<<16, 256, 0, s1>>>(W1, b1, W2);

    // main chain (legacy stream): detect -> count -> scan1(+dinv)
    detect_zero_kernel<<<(NTOKEN + 255) / 256, 256>>>(edge);
    count_kernel<<<(NEDGE + 255) / 256, 256>>>(edge);
    scan1_kernel<<<NSCANB, 256>>>();
    cudaEventRecord(ev1, 0);                 // dinv ready

    // matvec (needs dinv + Wc) overlaps scan2/scan3/scatter
    cudaStreamWaitEvent(s1, ev1, 0);
    matvec_kernel<<<((NTOKEN + 3) / 4 * 32 + 255) / 256, 256, 0, s1>>>(emb);
    cudaEventRecord(ev2, s1);

    scan2_kernel<<<1, 1024>>>();
    scan3_kernel<<<NSCANB, 256>>>();
    scatter_kernel<<<(NEDGE + 255) / 256, 256>>>(edge);

    // join, then aggregate + output
    cudaStreamWaitEvent(0, ev2, 0);
    agg_kernel<<<(NTOKEN * 32 + 255) / 256, 256>>>();
    out_kernel<<<(npos * 32 + 255) / 256, 256>>>(input, b2, out, npos);
}

// round 7
// speedup vs baseline: 3.4638x; 1.0474x over previous
#include <cuda_runtime.h>
#include <cuda_fp16.h>

#define NTOKEN 150000
#define NEDGE  2400000
#define NSCANB ((NTOKEN + 255) / 256)   // 586 scan tiles

// ---------------- scratch (static __device__, no allocation) ----------------
__device__ int    g_is64;
__device__ int    g_deg[NTOKEN];
__device__ int    g_off[NTOKEN];
__device__ int    g_cur[NTOKEN];
__device__ float  g_dinv[NTOKEN];
__device__ int    g_srcs[NEDGE];
__device__ __half g_Y2h[(size_t)NTOKEN * 64];  // 32  * dinv[v] * (emb[v] @ Wc)
__device__ __half g_g2h[(size_t)NTOKEN * 64];  // 1024* dinv[v] * h2[v]
__device__ float  g_Wc[64 * 64];               // W1 @ W2
__device__ float  g_bc[64];                    // b1 @ W2
__device__ int    g_bsum[NSCANB];
__device__ int    g_boff[NSCANB];

// Detect int64 vs int32 indices + zero degree array (one fused launch).
__global__ void detect_zero_kernel(const void* __restrict__ edge) {
    int i = blockIdx.x * blockDim.x + threadIdx.x;
    if (i < NTOKEN) g_deg[i] = 0;
    if (blockIdx.x == 0 && threadIdx.x == 0) {
        const unsigned long long* e = (const unsigned long long*)edge;
        int is64 = 1;
        for (int k = 0; k < 64; k++)
            if ((e[k] >> 32) != 0ull) { is64 = 0; break; }
        g_is64 = is64;
    }
}

// int32-view index load: little-endian int64 with values < 2^31 keeps the
// value in the low word -> read ints with stride 2.
__global__ void count_kernel(const void* __restrict__ edge) {
    int st = g_is64 ? 2 : 1;
    const int* e = (const int*)edge;
    long long i = (long long)blockIdx.x * blockDim.x + threadIdx.x;
    if (i < NEDGE) {
        int d = e[((long long)NEDGE + i) * st];
        atomicAdd(&g_deg[d], 1);
    }
}

// ---- 3-phase coalesced exclusive scan over g_deg ----
__global__ void scan1_kernel() {
    __shared__ int sh[256];
    int t = threadIdx.x;
    int i = blockIdx.x * 256 + t;
    int d = (i < NTOKEN) ? g_deg[i] : 0;
    if (i < NTOKEN) g_dinv[i] = rsqrtf((float)d + 1.0f);
    sh[t] = d;
    __syncthreads();
    for (int off = 128; off > 0; off >>= 1) {
        if (t < off) sh[t] += sh[t + off];
        __syncthreads();
    }
    if (t == 0) g_bsum[blockIdx.x] = sh[0];
}

__global__ void scan2_kernel() {
    __shared__ int sh[1024];
    int t = threadIdx.x;
    int v = (t < NSCANB) ? g_bsum[t] : 0;
    sh[t] = v;
    __syncthreads();
    for (int off = 1; off < 1024; off <<= 1) {
        int u = (t >= off) ? sh[t - off] : 0;
        __syncthreads();
        sh[t] += u;
        __syncthreads();
    }
    if (t < NSCANB) g_boff[t] = sh[t] - v;   // exclusive
}

__global__ void scan3_kernel() {
    __shared__ int sh[256];
    int t = threadIdx.x;
    int i = blockIdx.x * 256 + t;
    int d = (i < NTOKEN) ? g_deg[i] : 0;
    sh[t] = d;
    __syncthreads();
    for (int off = 1; off < 256; off <<= 1) {
        int u = (t >= off) ? sh[t - off] : 0;
        __syncthreads();
        sh[t] += u;
        __syncthreads();
    }
    if (i < NTOKEN) {
        int excl = sh[t] - d + g_boff[blockIdx.x];
        g_off[i] = excl;
        g_cur[i] = excl;
    }
}

__global__ void scatter_kernel(const void* __restrict__ edge) {
    int st = g_is64 ? 2 : 1;
    const int* e = (const int*)edge;
    long long i = (long long)blockIdx.x * blockDim.x + threadIdx.x;
    if (i < NEDGE) {
        int s = e[i * st];
        int d = e[((long long)NEDGE + i) * st];
        int pos = atomicAdd(&g_cur[d], 1);
        g_srcs[pos] = s;
    }
}

// Wc = W1 @ W2 (64x128 @ 128x64), bc = b1 @ W2. 16 blocks, one elem/thread.
__global__ void wc_kernel(const float* __restrict__ W1, const float* __restrict__ b1,
                          const float* __restrict__ W2) {
    int idx = blockIdx.x * 256 + threadIdx.x;   // 0..4095
    int i = idx >> 6, j = idx & 63;
    float s = 0.0f;
#pragma unroll 8
    for (int k = 0; k < 128; k++) s += W1[i * 128 + k] * W2[k * 64 + j];
    g_Wc[idx] = s;
    if (blockIdx.x == 0 && threadIdx.x < 64) {
        int t = threadIdx.x;
        float b = 0.0f;
#pragma unroll 8
        for (int k = 0; k < 128; k++) b += b1[k] * W2[k * 64 + t];
        g_bc[t] = b;
    }
}

// Y2h[v] = 32 * dinv[v] * (emb[v] @ Wc), fp16. 4 nodes per warp.
__global__ void matvec_kernel(const float* __restrict__ emb) {
    __shared__ float2 sWc[64 * 32];
    for (int i = threadIdx.x; i < 64 * 32; i += blockDim.x)
        sWc[i] = ((const float2*)g_Wc)[i];
    __syncthreads();
    int warp = (blockIdx.x * blockDim.x + threadIdx.x) >> 5;
    int lane = threadIdx.x & 31;
    int vb = warp * 4;
    if (vb >= NTOKEN) return;

    float2 x[4], a[4];
#pragma unroll
    for (int n = 0; n < 4; n++) {
        int v = vb + n;
        x[n] = (v < NTOKEN) ? ((const float2*)(emb + (size_t)v * 64))[lane]
                            : make_float2(0.f, 0.f);
        a[n] = make_float2(0.f, 0.f);
    }
#pragma unroll
    for (int k = 0; k < 64; k++) {
        float2 w = sWc[k * 32 + lane];
#pragma unroll
        for (int n = 0; n < 4; n++) {
            float xk = __shfl_sync(0xffffffffu, (k & 1) ? x[n].y : x[n].x, k >> 1);
            a[n].x += xk * w.x;
            a[n].y += xk * w.y;
        }
    }
#pragma unroll
    for (int n = 0; n < 4; n++) {
        int v = vb + n;
        if (v < NTOKEN) {
            float sc = 32.0f * g_dinv[v];
            ((__half2*)(g_Y2h + (size_t)v * 64))[lane] =
                __floats2half2_rn(a[n].x * sc, a[n].y * sc);
        }
    }
}

// g2h[v] = 1024 * dinv[v] * ( dinv[v]*(Y2[v]+sum Y2[s]) + bc )
//        = 32*dv*dv*accS + 1024*dv*bc   (accS = 32x-scaled fp32 accumulation)
__global__ void agg_kernel() {
    int v = (blockIdx.x * blockDim.x + threadIdx.x) >> 5;
    int lane = threadIdx.x & 31;
    if (v >= NTOKEN) return;
    float dv = g_dinv[v];
    float2 acc = __half22float2(((const __half2*)(g_Y2h + (size_t)v * 64))[lane]);
    int o = g_off[v];
    int d = g_deg[v];
    int j = 0;
    for (; j + 3 < d; j += 4) {
        int s0 = g_srcs[o + j], s1 = g_srcs[o + j + 1];
        int s2 = g_srcs[o + j + 2], s3 = g_srcs[o + j + 3];
        float2 y0 = __half22float2(((const __half2*)(g_Y2h + (size_t)s0 * 64))[lane]);
        float2 y1 = __half22float2(((const __half2*)(g_Y2h + (size_t)s1 * 64))[lane]);
        float2 y2 = __half22float2(((const __half2*)(g_Y2h + (size_t)s2 * 64))[lane]);
        float2 y3 = __half22float2(((const __half2*)(g_Y2h + (size_t)s3 * 64))[lane]);
        acc.x += y0.x + y1.x + y2.x + y3.x;
        acc.y += y0.y + y1.y + y2.y + y3.y;
    }
    for (; j < d; j++) {
        int s = g_srcs[o + j];
        float2 y = __half22float2(((const __half2*)(g_Y2h + (size_t)s * 64))[lane]);
        acc.x += y.x; acc.y += y.y;
    }
    float2 bc = ((const float2*)g_bc)[lane];
    float k1 = 32.0f * dv * dv;
    float k2 = 1024.0f * dv;
    ((__half2*)(g_g2h + (size_t)v * 64))[lane] =
        __floats2half2_rn(k1 * acc.x + k2 * bc.x, k1 * acc.y + k2 * bc.y);
}

// out[pos] = dinv[v]*(g2[v]+sum g2[s]) + b2 = dv*accS/1024 + b2
__global__ void out_kernel(const void* __restrict__ input, const float* __restrict__ b2,
                           float* __restrict__ out, int npos) {
    int st = g_is64 ? 2 : 1;
    const int* inp = (const int*)input;
    int w = (blockIdx.x * blockDim.x + threadIdx.x) >> 5;
    int lane = threadIdx.x & 31;
    if (w >= npos) return;
    int v = inp[(long long)w * st];
    float dv = g_dinv[v];
    float2 acc = __half22float2(((const __half2*)(g_g2h + (size_t)v * 64))[lane]);
    int o = g_off[v];
    int d = g_deg[v];
    int j = 0;
    for (; j + 3 < d; j += 4) {
        int s0 = g_srcs[o + j], s1 = g_srcs[o + j + 1];
        int s2 = g_srcs[o + j + 2], s3 = g_srcs[o + j + 3];
        float2 y0 = __half22float2(((const __half2*)(g_g2h + (size_t)s0 * 64))[lane]);
        float2 y1 = __half22float2(((const __half2*)(g_g2h + (size_t)s1 * 64))[lane]);
        float2 y2 = __half22float2(((const __half2*)(g_g2h + (size_t)s2 * 64))[lane]);
        float2 y3 = __half22float2(((const __half2*)(g_g2h + (size_t)s3 * 64))[lane]);
        acc.x += y0.x + y1.x + y2.x + y3.x;
        acc.y += y0.y + y1.y + y2.y + y3.y;
    }
    for (; j < d; j++) {
        int s = g_srcs[o + j];
        float2 y = __half22float2(((const __half2*)(g_g2h + (size_t)s * 64))[lane]);
        acc.x += y.x; acc.y += y.y;
    }
    float2 b = ((const float2*)b2)[lane];
    float inv = dv * (1.0f / 1024.0f);
    float2 r;
    r.x = inv * acc.x + b.x;
    r.y = inv * acc.y + b.y;
    ((float2*)(out + (size_t)w * 64))[lane] = r;
}

extern "C" void kernel_launch(void* const* d_in, const int* in_sizes, int n_in,
                              void* d_out, int out_size) {
    const float* emb = (const float*)d_in[0];
    const float* W1  = (const float*)d_in[1];
    const float* b1  = (const float*)d_in[2];
    const float* W2  = (const float*)d_in[3];
    const float* b2  = (const float*)d_in[4];
    const void*  input = d_in[5];
    const void*  edge  = d_in[7];
    float* out = (float*)d_out;
    int npos = in_sizes[5];  // B*L = 12800

    static cudaStream_t s1 = nullptr;
    static cudaEvent_t ev1 = nullptr, ev2 = nullptr;
    if (!s1) {
        cudaStreamCreateWithFlags(&s1, cudaStreamNonBlocking);
        cudaEventCreateWithFlags(&ev1, cudaEventDisableTiming);
        cudaEventCreateWithFlags(&ev2, cudaEventDisableTiming);
    }

    // dense side chain starts immediately: wc depends only on W1/b1/W2
    wc_kernel<<<16, 256, 0, s1>>>(W1, b1, W2);

    // main chain: detect -> count -> scan1(+dinv)
    detect_zero_kernel<<<(NTOKEN + 255) / 256, 256>>>(edge);
    count_kernel<<<(NEDGE + 255) / 256, 256>>>(edge);
    scan1_kernel<<<NSCANB, 256>>>();
    cudaEventRecord(ev1, 0);                 // dinv ready

    // matvec (needs dinv + Wc) overlaps scan2/scan3/scatter
    cudaStreamWaitEvent(s1, ev1, 0);
    matvec_kernel<<<((NTOKEN + 3) / 4 * 32 + 255) / 256, 256, 0, s1>>>(emb);
    cudaEventRecord(ev2, s1);

    scan2_kernel<<<1, 1024>>>();
    scan3_kernel<<<NSCANB, 256>>>();
    scatter_kernel<<<(NEDGE + 255) / 256, 256>>>(edge);

    // join, then aggregate + output
    cudaStreamWaitEvent(0, ev2, 0);
    agg_kernel<<<(NTOKEN * 32 + 255) / 256, 256>>>();
    out_kernel<<<(npos * 32 + 255) / 256, 256>>>(input, b2, out, npos);
}

// round 8
// speedup vs baseline: 3.4645x; 1.0002x over previous
#include <cuda_runtime.h>
#include <cuda_fp16.h>

#define NTOKEN 150000
#define NEDGE  2400000
#define NSCANB ((NTOKEN + 255) / 256)   // 586 scan tiles

// ---------------- scratch (static __device__, no allocation) ----------------
__device__ int    g_is64;
__device__ int    g_deg[NTOKEN];
__device__ int    g_off[NTOKEN];
__device__ float  g_dinv[NTOKEN];
__device__ int    g_rank[NEDGE];               // per-edge slot within its dst
__device__ int    g_srcs[NEDGE];               // CSR: src ids grouped by dst
__device__ __half g_Y2h[(size_t)NTOKEN * 64];  // 32  * dinv[v] * (emb[v] @ Wc)
__device__ __half g_g2h[(size_t)NTOKEN * 64];  // 1024* dinv[v] * h2[v]
__device__ float  g_Wc[64 * 64];               // W1 @ W2
__device__ float  g_bc[64];                    // b1 @ W2
__device__ int    g_bsum[NSCANB];

// Detect int64 vs int32 indices + zero degree array (one fused launch).
__global__ void detect_zero_kernel(const void* __restrict__ edge) {
    int i = blockIdx.x * blockDim.x + threadIdx.x;
    if (i < NTOKEN) g_deg[i] = 0;
    if (blockIdx.x == 0 && threadIdx.x == 0) {
        const unsigned long long* e = (const unsigned long long*)edge;
        int is64 = 1;
        for (int k = 0; k < 64; k++)
            if ((e[k] >> 32) != 0ull) { is64 = 0; break; }
        g_is64 = is64;
    }
}

// Count + rank in one pass: rank = this edge's slot within its dst's list.
// int32-view index load: little-endian int64 with values < 2^31 keeps the
// value in the low word -> read ints with stride 2.
__global__ void count_rank_kernel(const void* __restrict__ edge) {
    int st = g_is64 ? 2 : 1;
    const int* e = (const int*)edge;
    long long i = (long long)blockIdx.x * blockDim.x + threadIdx.x;
    if (i < NEDGE) {
        int d = e[((long long)NEDGE + i) * st];
        g_rank[i] = atomicAdd(&g_deg[d], 1);
    }
}

// scan1: per-tile degree sums + dinv.
__global__ void scan1_kernel() {
    __shared__ int sh[256];
    int t = threadIdx.x;
    int i = blockIdx.x * 256 + t;
    int d = (i < NTOKEN) ? g_deg[i] : 0;
    if (i < NTOKEN) g_dinv[i] = rsqrtf((float)d + 1.0f);
    sh[t] = d;
    __syncthreads();
    for (int off = 128; off > 0; off >>= 1) {
        if (t < off) sh[t] += sh[t + off];
        __syncthreads();
    }
    if (t == 0) g_bsum[blockIdx.x] = sh[0];
}

// scan3: each block redundantly computes its tile offset from g_bsum
// (586 L2-hot loads), then does the local exclusive scan and emits g_off.
__global__ void scan3_kernel() {
    __shared__ int sh[256];
    __shared__ int sboff;
    int t = threadIdx.x;
    // tile offset = sum of bsum[i] for i < blockIdx.x
    int partial = 0;
    for (int i = t; i < blockIdx.x; i += 256) partial += g_bsum[i];
    sh[t] = partial;
    __syncthreads();
    for (int off = 128; off > 0; off >>= 1) {
        if (t < off) sh[t] += sh[t + off];
        __syncthreads();
    }
    if (t == 0) sboff = sh[0];
    __syncthreads();
    // local exclusive scan of this tile's degrees
    int i = blockIdx.x * 256 + t;
    int d = (i < NTOKEN) ? g_deg[i] : 0;
    sh[t] = d;
    __syncthreads();
    for (int off = 1; off < 256; off <<= 1) {
        int u = (t >= off) ? sh[t - off] : 0;
        __syncthreads();
        sh[t] += u;
        __syncthreads();
    }
    if (i < NTOKEN) g_off[i] = sh[t] - d + sboff;
}

// Atomic-free scatter: pos = off[dst] + rank (rank from count pass).
__global__ void scatter_kernel(const void* __restrict__ edge) {
    int st = g_is64 ? 2 : 1;
    const int* e = (const int*)edge;
    long long i = (long long)blockIdx.x * blockDim.x + threadIdx.x;
    if (i < NEDGE) {
        int s = e[i * st];
        int d = e[((long long)NEDGE + i) * st];
        g_srcs[g_off[d] + g_rank[i]] = s;
    }
}

// Wc = W1 @ W2 (64x128 @ 128x64), bc = b1 @ W2. 16 blocks, one elem/thread.
__global__ void wc_kernel(const float* __restrict__ W1, const float* __restrict__ b1,
                          const float* __restrict__ W2) {
    int idx = blockIdx.x * 256 + threadIdx.x;   // 0..4095
    int i = idx >> 6, j = idx & 63;
    float s = 0.0f;
#pragma unroll 8
    for (int k = 0; k < 128; k++) s += W1[i * 128 + k] * W2[k * 64 + j];
    g_Wc[idx] = s;
    if (blockIdx.x == 0 && threadIdx.x < 64) {
        int t = threadIdx.x;
        float b = 0.0f;
#pragma unroll 8
        for (int k = 0; k < 128; k++) b += b1[k] * W2[k * 64 + t];
        g_bc[t] = b;
    }
}

// Y2h[v] = 32 * dinv[v] * (emb[v] @ Wc), fp16. 4 nodes per warp.
__global__ void matvec_kernel(const float* __restrict__ emb) {
    __shared__ float2 sWc[64 * 32];
    for (int i = threadIdx.x; i < 64 * 32; i += blockDim.x)
        sWc[i] = ((const float2*)g_Wc)[i];
    __syncthreads();
    int warp = (blockIdx.x * blockDim.x + threadIdx.x) >> 5;
    int lane = threadIdx.x & 31;
    int vb = warp * 4;
    if (vb >= NTOKEN) return;

    float2 x[4], a[4];
#pragma unroll
    for (int n = 0; n < 4; n++) {
        int v = vb + n;
        x[n] = (v < NTOKEN) ? ((const float2*)(emb + (size_t)v * 64))[lane]
                            : make_float2(0.f, 0.f);
        a[n] = make_float2(0.f, 0.f);
    }
#pragma unroll
    for (int k = 0; k < 64; k++) {
        float2 w = sWc[k * 32 + lane];
#pragma unroll
        for (int n = 0; n < 4; n++) {
            float xk = __shfl_sync(0xffffffffu, (k & 1) ? x[n].y : x[n].x, k >> 1);
            a[n].x += xk * w.x;
            a[n].y += xk * w.y;
        }
    }
#pragma unroll
    for (int n = 0; n < 4; n++) {
        int v = vb + n;
        if (v < NTOKEN) {
            float sc = 32.0f * g_dinv[v];
            ((__half2*)(g_Y2h + (size_t)v * 64))[lane] =
                __floats2half2_rn(a[n].x * sc, a[n].y * sc);
        }
    }
}

// g2h[v] = 1024 * dinv[v] * ( dinv[v]*(Y2[v]+sum Y2[s]) + bc )
//        = 32*dv*dv*accS + 1024*dv*bc   (accS = 32x-scaled fp32 accumulation)
__global__ void agg_kernel() {
    int v = (blockIdx.x * blockDim.x + threadIdx.x) >> 5;
    int lane = threadIdx.x & 31;
    if (v >= NTOKEN) return;
    float dv = g_dinv[v];
    float2 acc = __half22float2(((const __half2*)(g_Y2h + (size_t)v * 64))[lane]);
    int o = g_off[v];
    int d = g_deg[v];
    int j = 0;
    for (; j + 3 < d; j += 4) {
        int s0 = g_srcs[o + j], s1 = g_srcs[o + j + 1];
        int s2 = g_srcs[o + j + 2], s3 = g_srcs[o + j + 3];
        float2 y0 = __half22float2(((const __half2*)(g_Y2h + (size_t)s0 * 64))[lane]);
        float2 y1 = __half22float2(((const __half2*)(g_Y2h + (size_t)s1 * 64))[lane]);
        float2 y2 = __half22float2(((const __half2*)(g_Y2h + (size_t)s2 * 64))[lane]);
        float2 y3 = __half22float2(((const __half2*)(g_Y2h + (size_t)s3 * 64))[lane]);
        acc.x += y0.x + y1.x + y2.x + y3.x;
        acc.y += y0.y + y1.y + y2.y + y3.y;
    }
    for (; j < d; j++) {
        int s = g_srcs[o + j];
        float2 y = __half22float2(((const __half2*)(g_Y2h + (size_t)s * 64))[lane]);
        acc.x += y.x; acc.y += y.y;
    }
    float2 bc = ((const float2*)g_bc)[lane];
    float k1 = 32.0f * dv * dv;
    float k2 = 1024.0f * dv;
    ((__half2*)(g_g2h + (size_t)v * 64))[lane] =
        __floats2half2_rn(k1 * acc.x + k2 * bc.x, k1 * acc.y + k2 * bc.y);
}

// out[pos] = dinv[v]*(g2[v]+sum g2[s]) + b2 = dv*accS/1024 + b2
__global__ void out_kernel(const void* __restrict__ input, const float* __restrict__ b2,
                           float* __restrict__ out, int npos) {
    int st = g_is64 ? 2 : 1;
    const int* inp = (const int*)input;
    int w = (blockIdx.x * blockDim.x + threadIdx.x) >> 5;
    int lane = threadIdx.x & 31;
    if (w >= npos) return;
    int v = inp[(long long)w * st];
    float dv = g_dinv[v];
    float2 acc = __half22float2(((const __half2*)(g_g2h + (size_t)v * 64))[lane]);
    int o = g_off[v];
    int d = g_deg[v];
    int j = 0;
    for (; j + 3 < d; j += 4) {
        int s0 = g_srcs[o + j], s1 = g_srcs[o + j + 1];
        int s2 = g_srcs[o + j + 2], s3 = g_srcs[o + j + 3];
        float2 y0 = __half22float2(((const __half2*)(g_g2h + (size_t)s0 * 64))[lane]);
        float2 y1 = __half22float2(((const __half2*)(g_g2h + (size_t)s1 * 64))[lane]);
        float2 y2 = __half22float2(((const __half2*)(g_g2h + (size_t)s2 * 64))[lane]);
        float2 y3 = __half22float2(((const __half2*)(g_g2h + (size_t)s3 * 64))[lane]);
        acc.x += y0.x + y1.x + y2.x + y3.x;
        acc.y += y0.y + y1.y + y2.y + y3.y;
    }
    for (; j < d; j++) {
        int s = g_srcs[o + j];
        float2 y = __half22float2(((const __half2*)(g_g2h + (size_t)s * 64))[lane]);
        acc.x += y.x; acc.y += y.y;
    }
    float2 b = ((const float2*)b2)[lane];
    float inv = dv * (1.0f / 1024.0f);
    float2 r;
    r.x = inv * acc.x + b.x;
    r.y = inv * acc.y + b.y;
    ((float2*)(out + (size_t)w * 64))[lane] = r;
}

extern "C" void kernel_launch(void* const* d_in, const int* in_sizes, int n_in,
                              void* d_out, int out_size) {
    const float* emb = (const float*)d_in[0];
    const float* W1  = (const float*)d_in[1];
    const float* b1  = (const float*)d_in[2];
    const float* W2  = (const float*)d_in[3];
    const float* b2  = (const float*)d_in[4];
    const void*  input = d_in[5];
    const void*  edge  = d_in[7];
    float* out = (float*)d_out;
    int npos = in_sizes[5];  // B*L = 12800

    static cudaStream_t s1 = nullptr;
    static cudaEvent_t ev1 = nullptr, ev2 = nullptr;
    if (!s1) {
        cudaStreamCreateWithFlags(&s1, cudaStreamNonBlocking);
        cudaEventCreateWithFlags(&ev1, cudaEventDisableTiming);
        cudaEventCreateWithFlags(&ev2, cudaEventDisableTiming);
    }

    // dense side chain starts immediately: wc depends only on W1/b1/W2
    wc_kernel<<<16, 256, 0, s1>>>(W1, b1, W2);

    // main chain: detect -> count+rank -> scan1(+dinv)
    detect_zero_kernel<<<(NTOKEN + 255) / 256, 256>>>(edge);
    count_rank_kernel<<<(NEDGE + 255) / 256, 256>>>(edge);
    scan1_kernel<<<NSCANB, 256>>>();
    cudaEventRecord(ev1, 0);                 // dinv ready

    // matvec (needs dinv + Wc) overlaps scan3/scatter
    cudaStreamWaitEvent(s1, ev1, 0);
    matvec_kernel<<<((NTOKEN + 3) / 4 * 32 + 255) / 256, 256, 0, s1>>>(emb);
    cudaEventRecord(ev2, s1);

    scan3_kernel<<<NSCANB, 256>>>();
    scatter_kernel<<<(NEDGE + 255) / 256, 256>>>(edge);

    // join, then aggregate + output
    cudaStreamWaitEvent(0, ev2, 0);
    agg_kernel<<<(NTOKEN * 32 + 255) / 256, 256>>>();
    out_kernel<<<(npos * 32 + 255) / 256, 256>>>(input, b2, out, npos);
}

// round 9
// speedup vs baseline: 4.6182x; 1.3330x over previous
#include <cuda_runtime.h>
#include <cuda_fp16.h>

#define NTOKEN 150000
#define NEDGE  2400000
#define NSCANB ((NTOKEN + 255) / 256)   // 586 scan tiles

// ---------------- scratch (static __device__, no allocation) ----------------
__device__ int    g_is64;
__device__ int    g_deg[NTOKEN];
__device__ int    g_off[NTOKEN];
__device__ float  g_dinv[NTOKEN];
__device__ int    g_rank[NEDGE];               // per-edge slot within its dst
__device__ int    g_srcs[NEDGE];               // CSR: src ids grouped by dst
__device__ float  g_U[(size_t)NTOKEN * 64];    // unscaled emb @ Wc (fp32)
__device__ __half g_Y2h[(size_t)NTOKEN * 64];  // 32  * dinv[v] * U[v]
__device__ __half g_g2h[(size_t)NTOKEN * 64];  // 1024* dinv[v] * h2[v]
__device__ float  g_Wc[64 * 64];               // W1 @ W2
__device__ float  g_bc[64];                    // b1 @ W2
__device__ int    g_bsum[NSCANB];

// Detect int64 vs int32 indices + zero degree array (one fused launch).
__global__ void detect_zero_kernel(const void* __restrict__ edge) {
    int i = blockIdx.x * blockDim.x + threadIdx.x;
    if (i < NTOKEN) g_deg[i] = 0;
    if (blockIdx.x == 0 && threadIdx.x == 0) {
        const unsigned long long* e = (const unsigned long long*)edge;
        int is64 = 1;
        for (int k = 0; k < 64; k++)
            if ((e[k] >> 32) != 0ull) { is64 = 0; break; }
        g_is64 = is64;
    }
}

// Count + rank in one pass: rank = this edge's slot within its dst's list.
__global__ void count_rank_kernel(const void* __restrict__ edge) {
    int st = g_is64 ? 2 : 1;
    const int* e = (const int*)edge;
    long long i = (long long)blockIdx.x * blockDim.x + threadIdx.x;
    if (i < NEDGE) {
        int d = e[((long long)NEDGE + i) * st];
        g_rank[i] = atomicAdd(&g_deg[d], 1);
    }
}

// scan1: per-tile degree sums + dinv.
__global__ void scan1_kernel() {
    __shared__ int sh[256];
    int t = threadIdx.x;
    int i = blockIdx.x * 256 + t;
    int d = (i < NTOKEN) ? g_deg[i] : 0;
    if (i < NTOKEN) g_dinv[i] = rsqrtf((float)d + 1.0f);
    sh[t] = d;
    __syncthreads();
    for (int off = 128; off > 0; off >>= 1) {
        if (t < off) sh[t] += sh[t + off];
        __syncthreads();
    }
    if (t == 0) g_bsum[blockIdx.x] = sh[0];
}

// scan3: each block redundantly computes its tile offset from g_bsum
// (586 L2-hot loads), then does the local exclusive scan and emits g_off.
__global__ void scan3_kernel() {
    __shared__ int sh[256];
    __shared__ int sboff;
    int t = threadIdx.x;
    int partial = 0;
    for (int i = t; i < blockIdx.x; i += 256) partial += g_bsum[i];
    sh[t] = partial;
    __syncthreads();
    for (int off = 128; off > 0; off >>= 1) {
        if (t < off) sh[t] += sh[t + off];
        __syncthreads();
    }
    if (t == 0) sboff = sh[0];
    __syncthreads();
    int i = blockIdx.x * 256 + t;
    int d = (i < NTOKEN) ? g_deg[i] : 0;
    sh[t] = d;
    __syncthreads();
    for (int off = 1; off < 256; off <<= 1) {
        int u = (t >= off) ? sh[t - off] : 0;
        __syncthreads();
        sh[t] += u;
        __syncthreads();
    }
    if (i < NTOKEN) g_off[i] = sh[t] - d + sboff;
}

// Atomic-free scatter: pos = off[dst] + rank (rank from count pass).
__global__ void scatter_kernel(const void* __restrict__ edge) {
    int st = g_is64 ? 2 : 1;
    const int* e = (const int*)edge;
    long long i = (long long)blockIdx.x * blockDim.x + threadIdx.x;
    if (i < NEDGE) {
        int s = e[i * st];
        int d = e[((long long)NEDGE + i) * st];
        g_srcs[g_off[d] + g_rank[i]] = s;
    }
}

// Wc = W1 @ W2 (64x128 @ 128x64), bc = b1 @ W2. 16 blocks, one elem/thread.
__global__ void wc_kernel(const float* __restrict__ W1, const float* __restrict__ b1,
                          const float* __restrict__ W2) {
    int idx = blockIdx.x * 256 + threadIdx.x;   // 0..4095
    int i = idx >> 6, j = idx & 63;
    float s = 0.0f;
#pragma unroll 8
    for (int k = 0; k < 128; k++) s += W1[i * 128 + k] * W2[k * 64 + j];
    g_Wc[idx] = s;
    if (blockIdx.x == 0 && threadIdx.x < 64) {
        int t = threadIdx.x;
        float b = 0.0f;
#pragma unroll 8
        for (int k = 0; k < 128; k++) b += b1[k] * W2[k * 64 + t];
        g_bc[t] = b;
    }
}

// U[v] = emb[v] @ Wc (unscaled, fp32). No dinv dependency -> runs at t~0.
__global__ void matvecU_kernel(const float* __restrict__ emb) {
    __shared__ float2 sWc[64 * 32];
    for (int i = threadIdx.x; i < 64 * 32; i += blockDim.x)
        sWc[i] = ((const float2*)g_Wc)[i];
    __syncthreads();
    int warp = (blockIdx.x * blockDim.x + threadIdx.x) >> 5;
    int lane = threadIdx.x & 31;
    int vb = warp * 4;
    if (vb >= NTOKEN) return;

    float2 x[4], a[4];
#pragma unroll
    for (int n = 0; n < 4; n++) {
        int v = vb + n;
        x[n] = (v < NTOKEN) ? ((const float2*)(emb + (size_t)v * 64))[lane]
                            : make_float2(0.f, 0.f);
        a[n] = make_float2(0.f, 0.f);
    }
#pragma unroll
    for (int k = 0; k < 64; k++) {
        float2 w = sWc[k * 32 + lane];
#pragma unroll
        for (int n = 0; n < 4; n++) {
            float xk = __shfl_sync(0xffffffffu, (k & 1) ? x[n].y : x[n].x, k >> 1);
            a[n].x += xk * w.x;
            a[n].y += xk * w.y;
        }
    }
#pragma unroll
    for (int n = 0; n < 4; n++) {
        int v = vb + n;
        if (v < NTOKEN)
            ((float2*)(g_U + (size_t)v * 64))[lane] = a[n];
    }
}

// Y2h[v] = 32 * dinv[v] * U[v], fp16. Pure streaming pass (~58 MB).
__global__ void scale_kernel() {
    long long i = (long long)blockIdx.x * blockDim.x + threadIdx.x;  // NTOKEN*32
    if (i >= (long long)NTOKEN * 32) return;
    int v = (int)(i >> 5);
    float sc = 32.0f * g_dinv[v];
    float2 u = ((const float2*)g_U)[i];
    ((__half2*)g_Y2h)[i] = __floats2half2_rn(u.x * sc, u.y * sc);
}

// g2h[v] = 32*dv*dv*accS + 1024*dv*bc   (accS = 32x-scaled fp32 accumulation)
__global__ void agg_kernel() {
    int v = (blockIdx.x * blockDim.x + threadIdx.x) >> 5;
    int lane = threadIdx.x & 31;
    if (v >= NTOKEN) return;
    float dv = g_dinv[v];
    float2 acc = __half22float2(((const __half2*)(g_Y2h + (size_t)v * 64))[lane]);
    int o = g_off[v];
    int d = g_deg[v];
    int j = 0;
    for (; j + 3 < d; j += 4) {
        int s0 = g_srcs[o + j], s1 = g_srcs[o + j + 1];
        int s2 = g_srcs[o + j + 2], s3 = g_srcs[o + j + 3];
        float2 y0 = __half22float2(((const __half2*)(g_Y2h + (size_t)s0 * 64))[lane]);
        float2 y1 = __half22float2(((const __half2*)(g_Y2h + (size_t)s1 * 64))[lane]);
        float2 y2 = __half22float2(((const __half2*)(g_Y2h + (size_t)s2 * 64))[lane]);
        float2 y3 = __half22float2(((const __half2*)(g_Y2h + (size_t)s3 * 64))[lane]);
        acc.x += y0.x + y1.x + y2.x + y3.x;
        acc.y += y0.y + y1.y + y2.y + y3.y;
    }
    for (; j < d; j++) {
        int s = g_srcs[o + j];
        float2 y = __half22float2(((const __half2*)(g_Y2h + (size_t)s * 64))[lane]);
        acc.x += y.x; acc.y += y.y;
    }
    float2 bc = ((const float2*)g_bc)[lane];
    float k1 = 32.0f * dv * dv;
    float k2 = 1024.0f * dv;
    ((__half2*)(g_g2h + (size_t)v * 64))[lane] =
        __floats2half2_rn(k1 * acc.x + k2 * bc.x, k1 * acc.y + k2 * bc.y);
}

// out[pos] = dv*accS/1024 + b2
__global__ void out_kernel(const void* __restrict__ input, const float* __restrict__ b2,
                           float* __restrict__ out, int npos) {
    int st = g_is64 ? 2 : 1;
    const int* inp = (const int*)input;
    int w = (blockIdx.x * blockDim.x + threadIdx.x) >> 5;
    int lane = threadIdx.x & 31;
    if (w >= npos) return;
    int v = inp[(long long)w * st];
    float dv = g_dinv[v];
    float2 acc = __half22float2(((const __half2*)(g_g2h + (size_t)v * 64))[lane]);
    int o = g_off[v];
    int d = g_deg[v];
    int j = 0;
    for (; j + 3 < d; j += 4) {
        int s0 = g_srcs[o + j], s1 = g_srcs[o + j + 1];
        int s2 = g_srcs[o + j + 2], s3 = g_srcs[o + j + 3];
        float2 y0 = __half22float2(((const __half2*)(g_g2h + (size_t)s0 * 64))[lane]);
        float2 y1 = __half22float2(((const __half2*)(g_g2h + (size_t)s1 * 64))[lane]);
        float2 y2 = __half22float2(((const __half2*)(g_g2h + (size_t)s2 * 64))[lane]);
        float2 y3 = __half22float2(((const __half2*)(g_g2h + (size_t)s3 * 64))[lane]);
        acc.x += y0.x + y1.x + y2.x + y3.x;
        acc.y += y0.y + y1.y + y2.y + y3.y;
    }
    for (; j < d; j++) {
        int s = g_srcs[o + j];
        float2 y = __half22float2(((const __half2*)(g_g2h + (size_t)s * 64))[lane]);
        acc.x += y.x; acc.y += y.y;
    }
    float2 b = ((const float2*)b2)[lane];
    float inv = dv * (1.0f / 1024.0f);
    float2 r;
    r.x = inv * acc.x + b.x;
    r.y = inv * acc.y + b.y;
    ((float2*)(out + (size_t)w * 64))[lane] = r;
}

extern "C" void kernel_launch(void* const* d_in, const int* in_sizes, int n_in,
                              void* d_out, int out_size) {
    const float* emb = (const float*)d_in[0];
    const float* W1  = (const float*)d_in[1];
    const float* b1  = (const float*)d_in[2];
    const float* W2  = (const float*)d_in[3];
    const float* b2  = (const float*)d_in[4];
    const void*  input = d_in[5];
    const void*  edge  = d_in[7];
    float* out = (float*)d_out;
    int npos = in_sizes[5];  // B*L = 12800

    static cudaStream_t s1 = nullptr;
    static cudaEvent_t ev1 = nullptr, ev2 = nullptr;
    if (!s1) {
        cudaStreamCreateWithFlags(&s1, cudaStreamNonBlocking);
        cudaEventCreateWithFlags(&ev1, cudaEventDisableTiming);
        cudaEventCreateWithFlags(&ev2, cudaEventDisableTiming);
    }

    // dense side chain: wc -> matvecU, independent of the graph chain entirely
    wc_kernel<<<16, 256, 0, s1>>>(W1, b1, W2);
    matvecU_kernel<<<((NTOKEN + 3) / 4 * 32 + 255) / 256, 256, 0, s1>>>(emb);

    // main chain: detect -> count+rank -> scan1(+dinv)
    detect_zero_kernel<<<(NTOKEN + 255) / 256, 256>>>(edge);
    count_rank_kernel<<<(NEDGE + 255) / 256, 256>>>(edge);
    scan1_kernel<<<NSCANB, 256>>>();
    cudaEventRecord(ev1, 0);                 // dinv ready

    // scale (needs dinv + U) overlaps scan3/scatter
    cudaStreamWaitEvent(s1, ev1, 0);
    scale_kernel<<<((long long)NTOKEN * 32 + 255) / 256, 256, 0, s1>>>();
    cudaEventRecord(ev2, s1);

    scan3_kernel<<<NSCANB, 256>>>();
    scatter_kernel<<<(NEDGE + 255) / 256, 256>>>(edge);

    // join, then aggregate + output
    cudaStreamWaitEvent(0, ev2, 0);
    agg_kernel<<<(NTOKEN * 32 + 255) / 256, 256>>>();
    out_kernel<<<(npos * 32 + 255) / 256, 256>>>(input, b2, out, npos);
}